// round 9
// baseline (speedup 1.0000x reference)
#include <cuda_runtime.h>

#define NN  100000
#define EE  1600000
#define FIN 128
#define HH  64
#define CC  7
#define NBLK 391   // ceil(NN/256)

// Scratch (device globals — no allocation allowed)
__device__ __align__(16) float g_p1[NN * HH];
__device__ __align__(16) float g_r1[NN * HH];
__device__ __align__(16) float g_h[NN * HH];
__device__ __align__(16) float g_p2[NN * 8];
__device__ __align__(16) float g_r2[NN * 8];
// CSR build
__device__ int g_degi[NN];
__device__ int g_incl[NN];
__device__ int g_rowstart[NN];
__device__ int g_cursor[NN];
__device__ int g_bsum[512];
__device__ int g_boff[512];
__device__ int g_csr[EE];

// packed f32x2 helpers
#define PACK_DUP(p, x) \
    asm("mov.b64 %0, {%1, %1};" : "=l"(p) : "f"(x))
#define FFMA2(acc, a, b) \
    asm("fma.rn.f32x2 %0, %1, %2, %0;" : "+l"(acc) : "l"(a), "l"(b))
#define UNPACK2(lo, hi, p) \
    asm("mov.b64 {%0, %1}, %2;" : "=f"(lo), "=f"(hi) : "l"(p))

// ---------------------------------------------------------------------------
__global__ void k_zero_deg() {
    int i = blockIdx.x * blockDim.x + threadIdx.x;
    if (i < NN) g_degi[i] = 0;
}

__global__ void k_hist(const int* __restrict__ ei, int e) {
    int i = blockIdx.x * blockDim.x + threadIdx.x;
    if (i < e) atomicAdd(&g_degi[ei[e + i]], 1);
}

__global__ void k_scan1(int n) {
    __shared__ int s[256];
    int i = blockIdx.x * 256 + threadIdx.x;
    int v = (i < n) ? g_degi[i] : 0;
    s[threadIdx.x] = v;
    __syncthreads();
#pragma unroll
    for (int off = 1; off < 256; off <<= 1) {
        int t = (threadIdx.x >= off) ? s[threadIdx.x - off] : 0;
        __syncthreads();
        s[threadIdx.x] += t;
        __syncthreads();
    }
    if (i < n) g_incl[i] = s[threadIdx.x];
    if (threadIdx.x == 255) g_bsum[blockIdx.x] = s[255];
}

__global__ void k_scan2() {
    __shared__ int s[512];
    int t = threadIdx.x;
    int v = (t < NBLK) ? g_bsum[t] : 0;
    s[t] = v;
    __syncthreads();
#pragma unroll
    for (int off = 1; off < 512; off <<= 1) {
        int u = (t >= off) ? s[t - off] : 0;
        __syncthreads();
        s[t] += u;
        __syncthreads();
    }
    if (t < NBLK) g_boff[t] = s[t] - v;   // exclusive
}

__global__ void k_scan3(int n) {
    int i = blockIdx.x * blockDim.x + threadIdx.x;
    if (i >= n) return;
    int start = g_incl[i] - g_degi[i] + g_boff[i >> 8];
    g_rowstart[i] = start;
    g_cursor[i] = start;
}

__global__ void k_fill(const int* __restrict__ ei, int e) {
    int i = blockIdx.x * blockDim.x + threadIdx.x;
    if (i >= e) return;
    int src = ei[i];
    int dst = ei[e + i];
    int pos = atomicAdd(&g_cursor[dst], 1);
    g_csr[pos] = src;
}

// ---------------------------------------------------------------------------
// GEMM1 (f32x2 packed): p1 = x @ W1l ; r1 = x @ W1r + b1.
// 256 threads, 64 rows/block. Thread tile: 2 rows x 16 cols.
// smem: Ws[128][128] (W1l|W1r, stride 128), Xs[64][132] (padded).
#define XS_STRIDE 132
__global__ void k_gemm1(const float* __restrict__ x,
                        const float* __restrict__ W1l,
                        const float* __restrict__ W1r,
                        const float* __restrict__ b1, int n) {
    extern __shared__ float sm[];
    float* Ws = sm;                       // 128*128
    float* Xs = sm + FIN * 128;           // 64*132
    int t = threadIdx.x;

    for (int i = t; i < FIN * HH; i += 256) {
        int k = i / HH, c = i % HH;
        Ws[k * 128 + c]      = W1l[i];
        Ws[k * 128 + HH + c] = W1r[i];
    }
    int row0 = blockIdx.x * 64;
    for (int i = t; i < 64 * 32; i += 256) {     // float4 granularity
        int r = i >> 5, j = i & 31;
        int row = row0 + r;
        float4 v = make_float4(0.f, 0.f, 0.f, 0.f);
        if (row < n) v = ((const float4*)x)[(long)row * 32 + j];
        *(float4*)(Xs + r * XS_STRIDE + j * 4) = v;
    }
    __syncthreads();

    int tx = t & 7;    // 16-col group: cols tx*16 .. tx*16+15
    int ty = t >> 3;   // 2-row group:  rows ty*2, ty*2+1

    unsigned long long acc[2][8];
#pragma unroll
    for (int r = 0; r < 2; r++)
#pragma unroll
        for (int j = 0; j < 8; j++) acc[r][j] = 0ULL;

    const float* xs0 = Xs + (ty * 2) * XS_STRIDE;
    const float* xs1 = xs0 + XS_STRIDE;

#pragma unroll 2
    for (int k = 0; k < FIN; ++k) {
        const float* wr = Ws + k * 128 + tx * 16;
        ulonglong2 wa = *(const ulonglong2*)(wr);
        ulonglong2 wb = *(const ulonglong2*)(wr + 4);
        ulonglong2 wc = *(const ulonglong2*)(wr + 8);
        ulonglong2 wd = *(const ulonglong2*)(wr + 12);
        unsigned long long xp0, xp1;
        PACK_DUP(xp0, xs0[k]);
        PACK_DUP(xp1, xs1[k]);
        FFMA2(acc[0][0], xp0, wa.x); FFMA2(acc[0][1], xp0, wa.y);
        FFMA2(acc[0][2], xp0, wb.x); FFMA2(acc[0][3], xp0, wb.y);
        FFMA2(acc[0][4], xp0, wc.x); FFMA2(acc[0][5], xp0, wc.y);
        FFMA2(acc[0][6], xp0, wd.x); FFMA2(acc[0][7], xp0, wd.y);
        FFMA2(acc[1][0], xp1, wa.x); FFMA2(acc[1][1], xp1, wa.y);
        FFMA2(acc[1][2], xp1, wb.x); FFMA2(acc[1][3], xp1, wb.y);
        FFMA2(acc[1][4], xp1, wc.x); FFMA2(acc[1][5], xp1, wc.y);
        FFMA2(acc[1][6], xp1, wd.x); FFMA2(acc[1][7], xp1, wd.y);
    }

    // cols tx*16 .. tx*16+15 across the 128-wide (p1|r1) output
    bool isR = (tx >= 4);                  // cols >= 64 -> r1
    int cbase = (tx & 3) * 16;             // col offset within the 64-wide half
    float bb[16];
#pragma unroll
    for (int j = 0; j < 16; j++) bb[j] = isR ? __ldg(&b1[cbase + j]) : 0.f;
    float* outbuf = isR ? g_r1 : g_p1;

#pragma unroll
    for (int r = 0; r < 2; r++) {
        int row = row0 + ty * 2 + r;
        if (row >= n) continue;
        float o[16];
#pragma unroll
        for (int j = 0; j < 8; j++) {
            float lo, hi;
            UNPACK2(lo, hi, acc[r][j]);
            o[2 * j]     = lo + bb[2 * j];
            o[2 * j + 1] = hi + bb[2 * j + 1];
        }
        float4* dst = (float4*)(outbuf + (long)row * HH + cbase);
#pragma unroll
        for (int j = 0; j < 4; j++)
            dst[j] = make_float4(o[4 * j], o[4 * j + 1], o[4 * j + 2], o[4 * j + 3]);
    }
}

// ---------------------------------------------------------------------------
// Fused layer-1 aggregation: h = relu(mean_{src in N(dst)} p1[src] + r1[dst])
// 16 lanes per node, each lane owns one float4 column chunk. 4-way unroll.
__global__ void k_agg1(int n) {
    int tid = blockIdx.x * blockDim.x + threadIdx.x;
    int node = tid >> 4, q = tid & 15;
    if (node >= n) return;
    int start = g_rowstart[node];
    int d = g_degi[node];
    const float4* p1 = (const float4*)g_p1;
    float4 acc = make_float4(0.f, 0.f, 0.f, 0.f);
    int j = 0;
    for (; j + 4 <= d; j += 4) {
        int s0 = __ldg(&g_csr[start + j]);
        int s1 = __ldg(&g_csr[start + j + 1]);
        int s2 = __ldg(&g_csr[start + j + 2]);
        int s3 = __ldg(&g_csr[start + j + 3]);
        float4 v0 = __ldg(p1 + (long)s0 * 16 + q);
        float4 v1 = __ldg(p1 + (long)s1 * 16 + q);
        float4 v2 = __ldg(p1 + (long)s2 * 16 + q);
        float4 v3 = __ldg(p1 + (long)s3 * 16 + q);
        acc.x += (v0.x + v1.x) + (v2.x + v3.x);
        acc.y += (v0.y + v1.y) + (v2.y + v3.y);
        acc.z += (v0.z + v1.z) + (v2.z + v3.z);
        acc.w += (v0.w + v1.w) + (v2.w + v3.w);
    }
    for (; j < d; j++) {
        int s0 = __ldg(&g_csr[start + j]);
        float4 v0 = __ldg(p1 + (long)s0 * 16 + q);
        acc.x += v0.x; acc.y += v0.y; acc.z += v0.z; acc.w += v0.w;
    }
    float invd = 1.0f / fmaxf((float)d, 1.0f);
    float4 r = ((const float4*)g_r1)[(long)node * 16 + q];
    float4 o;
    o.x = fmaxf(acc.x * invd + r.x, 0.f);
    o.y = fmaxf(acc.y * invd + r.y, 0.f);
    o.z = fmaxf(acc.z * invd + r.z, 0.f);
    o.w = fmaxf(acc.w * invd + r.w, 0.f);
    ((float4*)g_h)[(long)node * 16 + q] = o;
}

// ---------------------------------------------------------------------------
// GEMM2: p2 = h @ W2l (pad 8), r2 = h @ W2r + b2 (pad 8)
__global__ void k_gemm2(const float* __restrict__ W2l,
                        const float* __restrict__ W2r,
                        const float* __restrict__ b2, int n) {
    __shared__ float hs[128 * 65];
    __shared__ float Wc[64 * 16];
    int t = threadIdx.x;
    int node0 = blockIdx.x * 128;

    for (int i = t; i < 64 * 16; i += 128) {
        int k = i >> 4, c = i & 15;
        float v = 0.f;
        if ((c & 7) < 7) v = (c < 8) ? W2l[k * 7 + c] : W2r[k * 7 + (c - 8)];
        Wc[i] = v;
    }
    for (int idx = t; idx < 128 * 64; idx += 128) {
        int row = idx >> 6, k = idx & 63;
        int node = node0 + row;
        hs[row * 65 + k] = (node < n) ? g_h[(long)node * 64 + k] : 0.f;
    }
    __syncthreads();

    int node = node0 + t;
    if (node >= n) return;

    float al[8], ar[8];
#pragma unroll
    for (int j = 0; j < 8; j++) { al[j] = 0.f; ar[j] = 0.f; }

#pragma unroll 4
    for (int k = 0; k < 64; ++k) {
        float hv = hs[t * 65 + k];
        const float* wr = Wc + k * 16;
        float4 a = *(const float4*)(wr);
        float4 b = *(const float4*)(wr + 4);
        float4 c = *(const float4*)(wr + 8);
        float4 d = *(const float4*)(wr + 12);
        al[0] += hv * a.x; al[1] += hv * a.y; al[2] += hv * a.z; al[3] += hv * a.w;
        al[4] += hv * b.x; al[5] += hv * b.y; al[6] += hv * b.z; al[7] += hv * b.w;
        ar[0] += hv * c.x; ar[1] += hv * c.y; ar[2] += hv * c.z; ar[3] += hv * c.w;
        ar[4] += hv * d.x; ar[5] += hv * d.y; ar[6] += hv * d.z; ar[7] += hv * d.w;
    }

    float bz[7];
#pragma unroll
    for (int c = 0; c < 7; c++) bz[c] = __ldg(&b2[c]);

    float4* p2o = (float4*)(g_p2 + (long)node * 8);
    p2o[0] = make_float4(al[0], al[1], al[2], al[3]);
    p2o[1] = make_float4(al[4], al[5], al[6], 0.f);
    float4* r2o = (float4*)(g_r2 + (long)node * 8);
    r2o[0] = make_float4(ar[0] + bz[0], ar[1] + bz[1], ar[2] + bz[2], ar[3] + bz[3]);
    r2o[1] = make_float4(ar[4] + bz[4], ar[5] + bz[5], ar[6] + bz[6], 0.f);
}

// ---------------------------------------------------------------------------
// Fused layer-2 aggregation + log_softmax: one thread per node.
__global__ void k_agg2(float* __restrict__ out, int n) {
    int node = blockIdx.x * blockDim.x + threadIdx.x;
    if (node >= n) return;
    int start = g_rowstart[node];
    int d = g_degi[node];
    const float4* p2 = (const float4*)g_p2;
    float4 a0 = make_float4(0.f, 0.f, 0.f, 0.f);
    float4 a1 = make_float4(0.f, 0.f, 0.f, 0.f);
    for (int j = 0; j < d; j++) {
        int s = __ldg(&g_csr[start + j]);
        float4 v0 = __ldg(p2 + (long)s * 2);
        float4 v1 = __ldg(p2 + (long)s * 2 + 1);
        a0.x += v0.x; a0.y += v0.y; a0.z += v0.z; a0.w += v0.w;
        a1.x += v1.x; a1.y += v1.y; a1.z += v1.z;
    }
    float invd = 1.0f / fmaxf((float)d, 1.0f);
    float4 r0 = ((const float4*)g_r2)[(long)node * 2];
    float4 r1 = ((const float4*)g_r2)[(long)node * 2 + 1];
    float v[7];
    v[0] = a0.x * invd + r0.x;
    v[1] = a0.y * invd + r0.y;
    v[2] = a0.z * invd + r0.z;
    v[3] = a0.w * invd + r0.w;
    v[4] = a1.x * invd + r1.x;
    v[5] = a1.y * invd + r1.y;
    v[6] = a1.z * invd + r1.z;
    float m = v[0];
#pragma unroll
    for (int c = 1; c < 7; c++) m = fmaxf(m, v[c]);
    float s = 0.f;
#pragma unroll
    for (int c = 0; c < 7; c++) s += expf(v[c] - m);
    float lse = m + logf(s);
#pragma unroll
    for (int c = 0; c < 7; c++) out[(long)node * 7 + c] = v[c] - lse;
}

// ---------------------------------------------------------------------------
extern "C" void kernel_launch(void* const* d_in, const int* in_sizes, int n_in,
                              void* d_out, int out_size) {
    const float* x   = (const float*)d_in[0];
    const int*   ei  = (const int*)d_in[1];
    const float* W1l = (const float*)d_in[2];
    const float* W1r = (const float*)d_in[3];
    const float* b1  = (const float*)d_in[4];
    const float* W2l = (const float*)d_in[5];
    const float* W2r = (const float*)d_in[6];
    const float* b2  = (const float*)d_in[7];
    float* out = (float*)d_out;

    int n = in_sizes[0] / FIN;
    int e = in_sizes[1] / 2;
    if (n > NN) n = NN;
    if (e > EE) e = EE;

    int smem1 = (FIN * 128 + 64 * XS_STRIDE) * (int)sizeof(float);
    cudaFuncSetAttribute(k_gemm1, cudaFuncAttributeMaxDynamicSharedMemorySize,
                         smem1);

    // CSR build
    k_zero_deg<<<NBLK, 256>>>();
    k_hist<<<(e + 255) / 256, 256>>>(ei, e);
    k_scan1<<<NBLK, 256>>>(n);
    k_scan2<<<1, 512>>>();
    k_scan3<<<NBLK, 256>>>(n);
    k_fill<<<(e + 255) / 256, 256>>>(ei, e);

    // Layer 1
    k_gemm1<<<(n + 63) / 64, 256, smem1>>>(x, W1l, W1r, b1, n);
    k_agg1<<<(n * 16 + 255) / 256, 256>>>(n);

    // Layer 2
    k_gemm2<<<(n + 127) / 128, 128>>>(W2l, W2r, b2, n);
    k_agg2<<<(n + 255) / 256, 256>>>(out, n);
}